// round 10
// baseline (speedup 1.0000x reference)
#include <cstdint>
#include <cuda_runtime.h>
#include <cuda_fp16.h>
#include <mma.h>

using namespace nvcuda;

// Problem constants
#define Mrows 16384
#define QKV_N 3072
#define Dn 1024

// Scratch (device globals: allocation-free)
__device__ float  g_qkv[(size_t)Mrows * QKV_N];    // 192 MB (fp32 qkv for attention)
__device__ __half g_attnh[(size_t)Mrows * Dn];     // 32 MB  (fp16 attention out)
__device__ __half g_xh[(size_t)Mrows * Dn];        // 32 MB  (fp16 x)
__device__ __half g_wqkvh[(size_t)Dn * QKV_N];     // 6 MB   (fp16 Wqkv)
__device__ __half g_wouth[(size_t)Dn * Dn];        // 2 MB   (fp16 Wout)

__device__ __forceinline__ void cp_async16(__half* smem_dst, const __half* gmem_src) {
    unsigned s = (unsigned)__cvta_generic_to_shared(smem_dst);
    asm volatile("cp.async.cg.shared.global [%0], [%1], 16;\n" :: "r"(s), "l"(gmem_src));
}
__device__ __forceinline__ void cp_commit() {
    asm volatile("cp.async.commit_group;\n" ::);
}
template<int N>
__device__ __forceinline__ void cp_wait() {
    asm volatile("cp.async.wait_group %0;\n" :: "n"(N));
}

// ---------------------------------------------------------------------------
// FP16 WMMA GEMM (fp32 accumulate), 3-stage cp.async pipeline.
// Block tile 128x128, BK=64, 4 warps (2x2), warp tile 64x64, 128 threads,
// 2 CTAs/SM. One barrier per K-tile; load issue interleaved with MMA.
// ---------------------------------------------------------------------------
#define BM 128
#define BN 128
#define BK 64
#define STAGES 3
#define A_LD (BK + 8)            // 72 halves (144B, mult of 16B)
#define B_LD (BN + 8)            // 136 halves (272B, mult of 16B)
#define A_STAGE (BM * A_LD)      // 9216 halves
#define B_STAGE (BK * B_LD)      // 8704 halves
#define SMEM_HALVES (STAGES * (A_STAGE + B_STAGE))
#define SMEM_BYTES (SMEM_HALVES * 2)   // 107520 B (x2 CTAs = 215KB < 228KB)

__global__ __launch_bounds__(128, 2)
void gemm_fp16_pipe_kernel(const __half* __restrict__ A,
                           const __half* __restrict__ B,
                           float* __restrict__ C,
                           int M, int N, int K)
{
    extern __shared__ __half smem[];
    __half* As = smem;                         // [STAGES][BM][A_LD]
    __half* Bs = smem + STAGES * A_STAGE;      // [STAGES][BK][B_LD]

    const int tid = threadIdx.x;
    const int warpId = tid >> 5;
    const int warpRow = warpId >> 1;      // 0..1  (64 rows each)
    const int warpCol = warpId & 1;       // 0..1  (64 cols each)

    const int rowBase = blockIdx.y * BM;
    const int colBase = blockIdx.x * BN;

    const int KT = K / BK;

    auto load_stage_full = [&](int kt, int stage) {
        const __half* Ag = A + (size_t)rowBase * K + kt * BK;
        const __half* Bg = B + (size_t)(kt * BK) * N + colBase;
        __half* Asm = As + stage * A_STAGE;
        __half* Bsm = Bs + stage * B_STAGE;
        #pragma unroll
        for (int i = 0; i < 8; i++) {
            int l = tid + i * 128;
            int ar = l >> 3, ac = (l & 7) << 3;
            cp_async16(Asm + ar * A_LD + ac, Ag + (size_t)ar * K + ac);
        }
        #pragma unroll
        for (int i = 0; i < 8; i++) {
            int l = tid + i * 128;
            int br = l >> 4, bc = (l & 15) << 3;
            cp_async16(Bsm + br * B_LD + bc, Bg + (size_t)br * N + bc);
        }
        cp_commit();
    };

    auto load_stage_part = [&](int kt, int stage, int part) {
        __half* Asm = As + stage * A_STAGE;
        __half* Bsm = Bs + stage * B_STAGE;
        if (part < 2) {
            const __half* Ag = A + (size_t)rowBase * K + kt * BK;
            #pragma unroll
            for (int i = 0; i < 4; i++) {
                int l = tid + (part * 4 + i) * 128;
                int ar = l >> 3, ac = (l & 7) << 3;
                cp_async16(Asm + ar * A_LD + ac, Ag + (size_t)ar * K + ac);
            }
        } else {
            const __half* Bg = B + (size_t)(kt * BK) * N + colBase;
            #pragma unroll
            for (int i = 0; i < 4; i++) {
                int l = tid + ((part - 2) * 4 + i) * 128;
                int br = l >> 4, bc = (l & 15) << 3;
                cp_async16(Bsm + br * B_LD + bc, Bg + (size_t)br * N + bc);
            }
        }
    };

    load_stage_full(0, 0);
    load_stage_full(1, 1);

    wmma::fragment<wmma::accumulator, 16, 16, 16, float> acc[4][4];
    #pragma unroll
    for (int m = 0; m < 4; m++)
        #pragma unroll
        for (int n = 0; n < 4; n++)
            wmma::fill_fragment(acc[m][n], 0.0f);

    for (int kt = 0; kt < KT; kt++) {
        cp_wait<STAGES - 2>();
        __syncthreads();   // single barrier per K-tile

        const bool doLoad = (kt + STAGES - 1 < KT);
        const int  ldStage = (kt + STAGES - 1) % STAGES;

        const __half* Asm = As + (kt % STAGES) * A_STAGE;
        const __half* Bsm = Bs + (kt % STAGES) * B_STAGE;

        #pragma unroll
        for (int kk = 0; kk < BK / 16; kk++) {
            wmma::fragment<wmma::matrix_a, 16, 16, 16, __half, wmma::row_major> af[4];
            wmma::fragment<wmma::matrix_b, 16, 16, 16, __half, wmma::row_major> bf[4];
            #pragma unroll
            for (int m = 0; m < 4; m++)
                wmma::load_matrix_sync(af[m], Asm + (warpRow * 64 + m * 16) * A_LD + kk * 16, A_LD);
            #pragma unroll
            for (int n = 0; n < 4; n++)
                wmma::load_matrix_sync(bf[n], Bsm + (kk * 16) * B_LD + warpCol * 64 + n * 16, B_LD);

            if (doLoad)
                load_stage_part(kt + STAGES - 1, ldStage, kk);

            #pragma unroll
            for (int m = 0; m < 4; m++)
                #pragma unroll
                for (int n = 0; n < 4; n++)
                    wmma::mma_sync(acc[m][n], af[m], bf[n], acc[m][n]);
        }
        cp_commit();
    }

    #pragma unroll
    for (int m = 0; m < 4; m++) {
        #pragma unroll
        for (int n = 0; n < 4; n++) {
            int r = rowBase + warpRow * 64 + m * 16;
            int c = colBase + warpCol * 64 + n * 16;
            wmma::store_matrix_sync(C + (size_t)r * N + c, acc[m][n], N, wmma::mem_row_major);
        }
    }
}

// ---------------------------------------------------------------------------
// Elementwise fp32 -> fp16 (RN) conversion
// ---------------------------------------------------------------------------
__global__ void f32_to_f16_kernel(const float4* __restrict__ in,
                                  __half2* __restrict__ out, int n4)
{
    int i = blockIdx.x * blockDim.x + threadIdx.x;
    if (i < n4) {
        float4 v = in[i];
        out[2 * i]     = __floats2half2_rn(v.x, v.y);
        out[2 * i + 1] = __floats2half2_rn(v.z, v.w);
    }
}

// ---------------------------------------------------------------------------
// Per-token head-attention v2: float4 LDS throughout.
// One block (256 thr) per token. fp32 math, fp16 output.
//   sq/sk rows: stride 17 float4 (68 floats) -> 16B-aligned, low conflicts
//   sv rows:    stride 16 float4 (64 floats)
// ---------------------------------------------------------------------------
#define QK_LD 17   // float4 stride for sq/sk rows

__global__ __launch_bounds__(256, 8)
void attn_kernel(const float* __restrict__ qkv, __half* __restrict__ out)
{
    __shared__ float4 sq[16 * QK_LD];
    __shared__ float4 sk[16 * QK_LD];
    __shared__ float4 sv[16 * 16];
    __shared__ float  sattn[16 * 16];

    const int t = blockIdx.x;
    const float4* base4 = reinterpret_cast<const float4*>(qkv + (size_t)t * QKV_N);
    const int tid = threadIdx.x;

    // Load 768 float4 (q,k,v: 256 each); 3 per thread
    #pragma unroll
    for (int c = 0; c < 3; c++) {
        int idx4 = tid + c * 256;          // [0,768)
        int arr  = idx4 >> 8;              // 0=q, 1=k, 2=v
        int r    = (idx4 & 255) >> 4;      // row 0..15
        int d4   = idx4 & 15;              // float4 col 0..15
        float4 v = base4[idx4];
        if (arr == 0)      sq[r * QK_LD + d4] = v;
        else if (arr == 1) sk[r * QK_LD + d4] = v;
        else               sv[r * 16 + d4]    = v;
    }
    __syncthreads();

    // Scores: thread (i,j) dots 16 float4 pairs
    const int i = tid >> 4, j = tid & 15;
    float s = 0.0f;
    #pragma unroll
    for (int d4 = 0; d4 < 16; d4++) {
        float4 a = sq[i * QK_LD + d4];
        float4 b = sk[j * QK_LD + d4];
        s += a.x * b.x + a.y * b.y + a.z * b.z + a.w * b.w;
    }
    s *= 0.125f;   // 1/sqrt(64)

    // Softmax over j (16-lane warp-aligned groups)
    float mx = s;
    #pragma unroll
    for (int off = 8; off; off >>= 1)
        mx = fmaxf(mx, __shfl_xor_sync(0xffffffffu, mx, off));
    float e = __expf(s - mx);
    float sum = e;
    #pragma unroll
    for (int off = 8; off; off >>= 1)
        sum += __shfl_xor_sync(0xffffffffu, sum, off);
    sattn[i * 16 + j] = e / sum;
    __syncthreads();

    // AV: thread handles (oi, od4): 4 contiguous outputs
    const int oi = tid >> 4, od4 = tid & 15;
    float4 acc = make_float4(0.f, 0.f, 0.f, 0.f);
    #pragma unroll
    for (int jj = 0; jj < 16; jj++) {
        float w = sattn[oi * 16 + jj];     // broadcast within oi-group
        float4 v = sv[jj * 16 + od4];
        acc.x += w * v.x; acc.y += w * v.y;
        acc.z += w * v.z; acc.w += w * v.w;
    }
    // fp16 output, 8B per thread, 128B per 16-lane group
    __half2* o2 = reinterpret_cast<__half2*>(out + (size_t)t * Dn + oi * 64 + od4 * 4);
    o2[0] = __floats2half2_rn(acc.x, acc.y);
    o2[1] = __floats2half2_rn(acc.z, acc.w);
}

// ---------------------------------------------------------------------------
extern "C" void kernel_launch(void* const* d_in, const int* in_sizes, int n_in,
                              void* d_out, int out_size)
{
    const float* x    = (const float*)d_in[0];
    const float* Wqkv = (const float*)d_in[1];
    const float* Wout = (const float*)d_in[2];
    float* out = (float*)d_out;

    float *qkv_p;
    __half *attnh_p, *xh_p, *wqkvh_p, *wouth_p;
    cudaGetSymbolAddress((void**)&qkv_p, g_qkv);
    cudaGetSymbolAddress((void**)&attnh_p, g_attnh);
    cudaGetSymbolAddress((void**)&xh_p, g_xh);
    cudaGetSymbolAddress((void**)&wqkvh_p, g_wqkvh);
    cudaGetSymbolAddress((void**)&wouth_p, g_wouth);

    static bool attr_set = false;
    if (!attr_set) {
        cudaFuncSetAttribute(gemm_fp16_pipe_kernel,
                             cudaFuncAttributeMaxDynamicSharedMemorySize, SMEM_BYTES);
        attr_set = true;
    }

    // Convert operands to fp16 (RN) once.
    {
        int n4x = (Mrows * Dn) / 4;
        f32_to_f16_kernel<<<(n4x + 255) / 256, 256>>>((const float4*)x, (__half2*)xh_p, n4x);
        int n4q = (Dn * QKV_N) / 4;
        f32_to_f16_kernel<<<(n4q + 255) / 256, 256>>>((const float4*)Wqkv, (__half2*)wqkvh_p, n4q);
        int n4o = (Dn * Dn) / 4;
        f32_to_f16_kernel<<<(n4o + 255) / 256, 256>>>((const float4*)Wout, (__half2*)wouth_p, n4o);
    }

    // GEMM1: qkv = x @ Wqkv   (16384 x 3072, K=1024), fp32 out
    {
        dim3 grid(QKV_N / BN, Mrows / BM);
        gemm_fp16_pipe_kernel<<<grid, 128, SMEM_BYTES>>>(xh_p, wqkvh_p, qkv_p,
                                                         Mrows, QKV_N, Dn);
    }

    // Attention per token (fp32 math, fp16 out)
    attn_kernel<<<Mrows, 256>>>(qkv_p, attnh_p);

    // GEMM2: out = attn @ Wout  (16384 x 1024, K=1024), fp32 out
    {
        dim3 grid(Dn / BN, Mrows / BM);
        gemm_fp16_pipe_kernel<<<grid, 128, SMEM_BYTES>>>(attnh_p, wouth_p, out,
                                                         Mrows, Dn, Dn);
    }
}